// round 16
// baseline (speedup 1.0000x reference)
#include <cuda_runtime.h>
#include <cuda_bf16.h>
#include <cstdint>

#define TPB 512
#define GRIDX 148
#define TILE_M 256
#define BETA 3.0f
#define MAXA 5.0f
#define SKEW_CYC 7000ULL   // ~1/4 of a tile; de-phases same-SMSP warps

// smem: interleaved bf16 hi/lo B layouts, 16B unit = [H0,H1,L0,L1] per (ks,q)
#define B1OFF  0        // 224 rows x 64B   (value rows 0..99, loc rows 112..211)
#define B2VOFF 14336    // 56 rows x 448B
#define B2LOFF 39424    // 104 rows x 448B
#define SMEM_BYTES 86016

// pack two f32 -> bf16x2 (lo=x, hi=y) plus residual word
__device__ __forceinline__ void split_pack(float x, float y, uint32_t& H, uint32_t& L) {
    asm("cvt.rn.bf16x2.f32 %0, %1, %2;" : "=r"(H) : "f"(y), "f"(x));
    float xh = __uint_as_float(H << 16);
    float yh = __uint_as_float(H & 0xFFFF0000u);
    float xr = x - xh, yr = y - yh;
    asm("cvt.rn.bf16x2.f32 %0, %1, %2;" : "=r"(L) : "f"(yr), "f"(xr));
}
__device__ __forceinline__ void relu_split(float x, float y, uint32_t& H, uint32_t& L) {
    split_pack(fmaxf(x, 0.f), fmaxf(y, 0.f), H, L);
}

// staging: write bf16 hi at byte bH, lo at bH+8
__device__ __forceinline__ void st_split(char* sm, int bH, float v) {
    __nv_bfloat16 h = __float2bfloat16(v);
    float r = v - __bfloat162float(h);
    __nv_bfloat16 l = __float2bfloat16(r);
    *(unsigned short*)(sm + bH)     = *(unsigned short*)&h;
    *(unsigned short*)(sm + bH + 8) = *(unsigned short*)&l;
}
// interleaved byte offsets (H slot; L at +8)
__device__ __forceinline__ int b1_byte(int row, int k) {
    int w = k >> 1;
    return row * 64 + (w & 3) * 16 + ((w >> 2) << 2) + ((k & 1) << 1);
}
__device__ __forceinline__ int b2_byte(int row, int k) {
    int w = k >> 1;
    return row * 448 + (w >> 3) * 64 + ((w & 3) << 4) + (((w >> 2) & 1) << 2) + ((k & 1) << 1);
}

// VOLATILE on purpose: prevents ptxas from hoisting/pipelining MMAs, which
// explodes live ranges and spills (R7/R8/R9 regressions all traced to
// non-volatile here). Do not remove volatile.
__device__ __forceinline__ void mma16816(float* c, const uint32_t* a, uint32_t b0, uint32_t b1) {
    asm volatile(
        "mma.sync.aligned.m16n8k16.row.col.f32.bf16.bf16.f32 "
        "{%0,%1,%2,%3}, {%4,%5,%6,%7}, {%8,%9}, {%0,%1,%2,%3};"
        : "+f"(c[0]), "+f"(c[1]), "+f"(c[2]), "+f"(c[3])
        : "r"(a[0]), "r"(a[1]), "r"(a[2]), "r"(a[3]), "r"(b0), "r"(b1));
}

__device__ __forceinline__ float fast_tanh(float x) {
    float e = __expf(2.0f * x);
    return 1.0f - __fdividef(2.0f, e + 1.0f);
}

__global__ __launch_bounds__(TPB, 1)
void net_kernel(const float* __restrict__ s,  const float* __restrict__ a,
                const float* __restrict__ wv1, const float* __restrict__ bv1,
                const float* __restrict__ wv2, const float* __restrict__ bv2,
                const float* __restrict__ wl1, const float* __restrict__ bl1,
                const float* __restrict__ wl2, const float* __restrict__ bl2,
                float* __restrict__ out, int nrows)
{
    extern __shared__ __align__(16) char sm[];
    const int tid  = threadIdx.x;
    const int w    = tid >> 5;
    const int lane = tid & 31;
    const int g    = lane >> 2;
    const int q    = lane & 3;

    // zero all smem (covers every pad row/col)
    for (int i = tid * 16; i < SMEM_BYTES; i += TPB * 16)
        *(float4*)(sm + i) = make_float4(0.f, 0.f, 0.f, 0.f);
    __syncthreads();

    // ---- stage weights ----
    // B1: value rows 0..99, loc rows 112..211; k<10 = w1[k][n], k=10 = bias
    for (int i = tid; i < 2200; i += TPB) {
        int tower = i / 1100, rem = i % 1100, n = rem / 11, k = rem % 11;
        float v = (k < 10) ? (tower ? wl1[k * 100 + n] : wv1[k * 100 + n])
                           : (tower ? bl1[n] : bv1[n]);
        st_split(sm, B1OFF + b1_byte(tower ? 112 + n : n, k), v);
    }
    // B2v: permuted rows sigma(c); k<100 = wv2[k][sig], k=100 = bias
    for (int i = tid; i < 56 * 101; i += TPB) {
        int c = i / 101, k = i % 101;
        int sig = (c % 8) / 2 + 8 * (c / 8) + 4 * (c % 2);
        if (sig < 50)
            st_split(sm, B2VOFF + b2_byte(c, k), (k < 100) ? wv2[k * 50 + sig] : bv2[sig]);
    }
    // B2l: row c = 2n+comp
    for (int i = tid; i < 100 * 101; i += TPB) {
        int c = i / 101, k = i % 101;
        float v = (k < 100) ? wl2[(c >> 1) * 200 + k * 2 + (c & 1)] : bl2[c];
        st_split(sm, B2LOFF + b2_byte(c, k), v);
    }
    __syncthreads();

    // ---- de-phase same-SMSP warps (SMSP = w%4; rank = w>>2) ----
    // One-time skew so the 4 warps sharing each scheduler hit tensor phases
    // at different times; no intra-loop syncs exist, so the stagger persists.
    {
        unsigned long long skew = (unsigned long long)(w >> 2) * SKEW_CYC;
        if (skew) {
            unsigned long long t0 = clock64();
            while (clock64() - t0 < skew) { }
        }
    }

    const int ntiles = (nrows + TILE_M - 1) / TILE_M;
    const int lr0 = w * 16 + g;

    // loop-invariant base pointers; all LDS offsets below are compile-time immediates
    const char* pB1 = sm + g * 64  + q * 16;   // B1: + j*512 (+ 112*64 for loc tower)
    const char* pB2 = sm + g * 448 + q * 16;   // B2: + B2xOFF + j*3584 + ks*64

    for (int tile = blockIdx.x; tile < ntiles; tile += GRIDX) {
        const int grow0 = tile * TILE_M + lr0;
        const int grow1 = grow0 + 8;

        // ---- GEMM1 A-fragments from global s (K=16: s cols 0..9, bias at 10) ----
        uint32_t saH[4], saL[4];
        {
            float2 p0 = make_float2(0.f, 0.f), p1 = p0, e0 = p0, e1 = p0;
            if (grow0 < nrows) p0 = *(const float2*)(s + (size_t)grow0 * 10 + 2 * q);
            if (grow1 < nrows) p1 = *(const float2*)(s + (size_t)grow1 * 10 + 2 * q);
            if (q == 0) {
                if (grow0 < nrows) e0 = *(const float2*)(s + (size_t)grow0 * 10 + 8);
                if (grow1 < nrows) e1 = *(const float2*)(s + (size_t)grow1 * 10 + 8);
            } else if (q == 1) {
                e0.x = 1.0f; e1.x = 1.0f;
            }
            split_pack(p0.x, p0.y, saH[0], saL[0]);
            split_pack(p1.x, p1.y, saH[1], saL[1]);
            split_pack(e0.x, e0.y, saH[2], saL[2]);
            split_pack(e1.x, e1.y, saH[3], saL[3]);
        }

        // ======== GEMM1v with rolling-pair convert (dv live = 2 tiles) ========
        uint32_t vaH[7][4], vaL[7][4];
        #pragma unroll
        for (int jp = 0; jp < 6; jp++) {
            float d0[4] = {0.f, 0.f, 0.f, 0.f}, d1[4] = {0.f, 0.f, 0.f, 0.f};
            {
                uint4 bb = *(const uint4*)(pB1 + (2 * jp) * 512);
                mma16816(d0, saH, bb.x, bb.y);
                mma16816(d0, saH, bb.z, bb.w);
                mma16816(d0, saL, bb.x, bb.y);
            }
            {
                uint4 bb = *(const uint4*)(pB1 + (2 * jp + 1) * 512);
                mma16816(d1, saH, bb.x, bb.y);
                mma16816(d1, saH, bb.z, bb.w);
                mma16816(d1, saL, bb.x, bb.y);
            }
            relu_split(d0[0], d0[1], vaH[jp][0], vaL[jp][0]);
            relu_split(d0[2], d0[3], vaH[jp][1], vaL[jp][1]);
            relu_split(d1[0], d1[1], vaH[jp][2], vaL[jp][2]);
            relu_split(d1[2], d1[3], vaH[jp][3], vaL[jp][3]);
        }
        {
            float d0[4] = {0.f, 0.f, 0.f, 0.f};
            uint4 bb = *(const uint4*)(pB1 + 12 * 512);
            mma16816(d0, saH, bb.x, bb.y);
            mma16816(d0, saH, bb.z, bb.w);
            mma16816(d0, saL, bb.x, bb.y);
            relu_split(d0[0], d0[1], vaH[6][0], vaL[6][0]);
            relu_split(d0[2], d0[3], vaH[6][1], vaL[6][1]);
        }
        if (q == 2) { vaH[6][0] = 0x3F80u; vaL[6][0] = 0u; vaH[6][1] = 0x3F80u; vaL[6][1] = 0u; }
        vaH[6][2] = 0u; vaH[6][3] = 0u; vaL[6][2] = 0u; vaL[6][3] = 0u;

        // ===== GEMM2v: depth-1 rolling LDS prefetch (c = current, n = next) =====
        float cv[7][4];
        #pragma unroll
        for (int j = 0; j < 7; j++) { cv[j][0]=0.f; cv[j][1]=0.f; cv[j][2]=0.f; cv[j][3]=0.f; }
        {
            const char* pv = pB2 + B2VOFF;
            uint4 c = *(const uint4*)(pv);   // (ks=0, j=0)
            #pragma unroll
            for (int ks = 0; ks < 7; ks++) {
                #pragma unroll
                for (int j = 0; j < 7; j++) {
                    const int ni = (j < 6) ? (ks * 64 + (j + 1) * 3584)
                                           : ((ks < 6) ? ((ks + 1) * 64)
                                                       : (6 * 64 + 6 * 3584));  // harmless reload at end
                    uint4 n = *(const uint4*)(pv + ni);
                    mma16816(cv[j], vaH[ks], c.x, c.y);
                    mma16816(cv[j], vaH[ks], c.z, c.w);
                    mma16816(cv[j], vaL[ks], c.x, c.y);
                    c = n;
                }
            }
        }

        // ======== GEMM1l with rolling-pair convert (dl live = 2 tiles; va dead) ========
        uint32_t laH[7][4], laL[7][4];
        #pragma unroll
        for (int jp = 0; jp < 6; jp++) {
            float d0[4] = {0.f, 0.f, 0.f, 0.f}, d1[4] = {0.f, 0.f, 0.f, 0.f};
            {
                uint4 bb = *(const uint4*)(pB1 + 112 * 64 + (2 * jp) * 512);
                mma16816(d0, saH, bb.x, bb.y);
                mma16816(d0, saH, bb.z, bb.w);
                mma16816(d0, saL, bb.x, bb.y);
            }
            {
                uint4 bb = *(const uint4*)(pB1 + 112 * 64 + (2 * jp + 1) * 512);
                mma16816(d1, saH, bb.x, bb.y);
                mma16816(d1, saH, bb.z, bb.w);
                mma16816(d1, saL, bb.x, bb.y);
            }
            relu_split(d0[0], d0[1], laH[jp][0], laL[jp][0]);
            relu_split(d0[2], d0[3], laH[jp][1], laL[jp][1]);
            relu_split(d1[0], d1[1], laH[jp][2], laL[jp][2]);
            relu_split(d1[2], d1[3], laH[jp][3], laL[jp][3]);
        }
        {
            float d0[4] = {0.f, 0.f, 0.f, 0.f};
            uint4 bb = *(const uint4*)(pB1 + 112 * 64 + 12 * 512);
            mma16816(d0, saH, bb.x, bb.y);
            mma16816(d0, saH, bb.z, bb.w);
            mma16816(d0, saL, bb.x, bb.y);
            relu_split(d0[0], d0[1], laH[6][0], laL[6][0]);
            relu_split(d0[2], d0[3], laH[6][1], laL[6][1]);
        }
        if (q == 2) { laH[6][0] = 0x3F80u; laL[6][0] = 0u; laH[6][1] = 0x3F80u; laL[6][1] = 0u; }
        laH[6][2] = 0u; laH[6][3] = 0u; laL[6][2] = 0u; laL[6][3] = 0u;

        // action rows
        float2 av0 = make_float2(0.f, 0.f), av1 = av0;
        if (grow0 < nrows) av0 = ((const float2*)a)[grow0];
        if (grow1 < nrows) av1 = ((const float2*)a)[grow1];

        // ===== GEMM2l per-j + fused epilogue, depth-1 rolling LDS prefetch =====
        float ws0 = 0.f, vs0 = 0.f, ws1 = 0.f, vs1 = 0.f;
        {
            const char* pl = pB2 + B2LOFF;
            uint4 c = *(const uint4*)(pl);   // (j=0, ks=0)
            #pragma unroll
            for (int j = 0; j < 13; j++) {
                float lc[4] = {0.f, 0.f, 0.f, 0.f};
                #pragma unroll
                for (int ks = 0; ks < 7; ks++) {
                    const int ni = (ks < 6) ? (j * 3584 + (ks + 1) * 64)
                                            : ((j < 12) ? ((j + 1) * 3584)
                                                        : (12 * 3584 + 6 * 64));  // harmless reload at end
                    uint4 n = *(const uint4*)(pl + ni);
                    mma16816(lc, laH[ks], c.x, c.y);
                    mma16816(lc, laH[ks], c.z, c.w);
                    mma16816(lc, laL[ks], c.x, c.y);
                    c = n;
                }
                const bool valid = (4 * j + q) < 50;
                {
                    float tx = MAXA * fast_tanh(lc[0]) - av0.x;
                    float ty = MAXA * fast_tanh(lc[1]) - av0.y;
                    float e = valid ? __expf(-BETA * sqrtf(tx * tx + ty * ty)) : 0.f;
                    float cc = (j & 1) ? cv[j >> 1][1] : cv[j >> 1][0];
                    ws0 += e; vs0 += e * cc;
                }
                {
                    float tx = MAXA * fast_tanh(lc[2]) - av1.x;
                    float ty = MAXA * fast_tanh(lc[3]) - av1.y;
                    float e = valid ? __expf(-BETA * sqrtf(tx * tx + ty * ty)) : 0.f;
                    float cc = (j & 1) ? cv[j >> 1][3] : cv[j >> 1][2];
                    ws1 += e; vs1 += e * cc;
                }
            }
        }

        ws0 += __shfl_xor_sync(0xffffffffu, ws0, 1);
        vs0 += __shfl_xor_sync(0xffffffffu, vs0, 1);
        ws1 += __shfl_xor_sync(0xffffffffu, ws1, 1);
        vs1 += __shfl_xor_sync(0xffffffffu, vs1, 1);
        ws0 += __shfl_xor_sync(0xffffffffu, ws0, 2);
        vs0 += __shfl_xor_sync(0xffffffffu, vs0, 2);
        ws1 += __shfl_xor_sync(0xffffffffu, ws1, 2);
        vs1 += __shfl_xor_sync(0xffffffffu, vs1, 2);
        if (q == 0) {
            if (grow0 < nrows) out[grow0] = vs0 / ws0;
            if (grow1 < nrows) out[grow1] = vs1 / ws1;
        }
    }
}

extern "C" void kernel_launch(void* const* d_in, const int* in_sizes, int n_in,
                              void* d_out, int out_size)
{
    const float* s   = (const float*)d_in[0];
    const float* a   = (const float*)d_in[1];
    const float* wv1 = (const float*)d_in[2];
    const float* bv1 = (const float*)d_in[3];
    const float* wv2 = (const float*)d_in[4];
    const float* bv2 = (const float*)d_in[5];
    const float* wl1 = (const float*)d_in[6];
    const float* bl1 = (const float*)d_in[7];
    const float* wl2 = (const float*)d_in[8];
    const float* bl2 = (const float*)d_in[9];
    float* out = (float*)d_out;

    int nrows = in_sizes[0] / 10;

    cudaFuncSetAttribute(net_kernel, cudaFuncAttributeMaxDynamicSharedMemorySize, SMEM_BYTES);
    net_kernel<<<GRIDX, TPB, SMEM_BYTES>>>(s, a, wv1, bv1, wv2, bv2,
                                           wl1, bl1, wl2, bl2, out, nrows);
}

// round 17
// speedup vs baseline: 1.0353x; 1.0353x over previous
#include <cuda_runtime.h>
#include <cuda_bf16.h>
#include <cstdint>

#define TPB 512
#define GRIDX 148
#define TILE_M 256
#define BETA 3.0f
#define MAXA 5.0f

// smem: interleaved bf16 hi/lo B layouts, 16B unit = [H0,H1,L0,L1] per (ks,q)
#define B1OFF  0        // 224 rows x 64B   (value rows 0..99, loc rows 112..211)
#define B2VOFF 14336    // 56 rows x 448B
#define B2LOFF 39424    // 104 rows x 448B
#define SMEM_BYTES 86016

// pack two f32 -> bf16x2 (lo=x, hi=y) plus residual word
__device__ __forceinline__ void split_pack(float x, float y, uint32_t& H, uint32_t& L) {
    asm("cvt.rn.bf16x2.f32 %0, %1, %2;" : "=r"(H) : "f"(y), "f"(x));
    float xh = __uint_as_float(H << 16);
    float yh = __uint_as_float(H & 0xFFFF0000u);
    float xr = x - xh, yr = y - yh;
    asm("cvt.rn.bf16x2.f32 %0, %1, %2;" : "=r"(L) : "f"(yr), "f"(xr));
}
__device__ __forceinline__ void relu_split(float x, float y, uint32_t& H, uint32_t& L) {
    split_pack(fmaxf(x, 0.f), fmaxf(y, 0.f), H, L);
}

// staging: write bf16 hi at byte bH, lo at bH+8
__device__ __forceinline__ void st_split(char* sm, int bH, float v) {
    __nv_bfloat16 h = __float2bfloat16(v);
    float r = v - __bfloat162float(h);
    __nv_bfloat16 l = __float2bfloat16(r);
    *(unsigned short*)(sm + bH)     = *(unsigned short*)&h;
    *(unsigned short*)(sm + bH + 8) = *(unsigned short*)&l;
}
// interleaved byte offsets (H slot; L at +8)
__device__ __forceinline__ int b1_byte(int row, int k) {
    int w = k >> 1;
    return row * 64 + (w & 3) * 16 + ((w >> 2) << 2) + ((k & 1) << 1);
}
__device__ __forceinline__ int b2_byte(int row, int k) {
    int w = k >> 1;
    return row * 448 + (w >> 3) * 64 + ((w & 3) << 4) + (((w >> 2) & 1) << 2) + ((k & 1) << 1);
}

// VOLATILE on purpose: prevents ptxas from hoisting/pipelining MMAs, which
// explodes live ranges and spills (R7/R8/R9 regressions all traced to
// non-volatile here). Do not remove volatile. Latency hiding is created in
// SOURCE order: pair-interleaved accumulators + rolling LDS prefetch.
__device__ __forceinline__ void mma16816(float* c, const uint32_t* a, uint32_t b0, uint32_t b1) {
    asm volatile(
        "mma.sync.aligned.m16n8k16.row.col.f32.bf16.bf16.f32 "
        "{%0,%1,%2,%3}, {%4,%5,%6,%7}, {%8,%9}, {%0,%1,%2,%3};"
        : "+f"(c[0]), "+f"(c[1]), "+f"(c[2]), "+f"(c[3])
        : "r"(a[0]), "r"(a[1]), "r"(a[2]), "r"(a[3]), "r"(b0), "r"(b1));
}

__device__ __forceinline__ float fast_tanh(float x) {
    float e = __expf(2.0f * x);
    return 1.0f - __fdividef(2.0f, e + 1.0f);
}

__global__ __launch_bounds__(TPB, 1)
void net_kernel(const float* __restrict__ s,  const float* __restrict__ a,
                const float* __restrict__ wv1, const float* __restrict__ bv1,
                const float* __restrict__ wv2, const float* __restrict__ bv2,
                const float* __restrict__ wl1, const float* __restrict__ bl1,
                const float* __restrict__ wl2, const float* __restrict__ bl2,
                float* __restrict__ out, int nrows)
{
    extern __shared__ __align__(16) char sm[];
    const int tid  = threadIdx.x;
    const int w    = tid >> 5;
    const int lane = tid & 31;
    const int g    = lane >> 2;
    const int q    = lane & 3;

    // zero all smem (covers every pad row/col)
    for (int i = tid * 16; i < SMEM_BYTES; i += TPB * 16)
        *(float4*)(sm + i) = make_float4(0.f, 0.f, 0.f, 0.f);
    __syncthreads();

    // ---- stage weights ----
    // B1: value rows 0..99, loc rows 112..211; k<10 = w1[k][n], k=10 = bias
    for (int i = tid; i < 2200; i += TPB) {
        int tower = i / 1100, rem = i % 1100, n = rem / 11, k = rem % 11;
        float v = (k < 10) ? (tower ? wl1[k * 100 + n] : wv1[k * 100 + n])
                           : (tower ? bl1[n] : bv1[n]);
        st_split(sm, B1OFF + b1_byte(tower ? 112 + n : n, k), v);
    }
    // B2v: permuted rows sigma(c); k<100 = wv2[k][sig], k=100 = bias
    for (int i = tid; i < 56 * 101; i += TPB) {
        int c = i / 101, k = i % 101;
        int sig = (c % 8) / 2 + 8 * (c / 8) + 4 * (c % 2);
        if (sig < 50)
            st_split(sm, B2VOFF + b2_byte(c, k), (k < 100) ? wv2[k * 50 + sig] : bv2[sig]);
    }
    // B2l: row c = 2n+comp
    for (int i = tid; i < 100 * 101; i += TPB) {
        int c = i / 101, k = i % 101;
        float v = (k < 100) ? wl2[(c >> 1) * 200 + k * 2 + (c & 1)] : bl2[c];
        st_split(sm, B2LOFF + b2_byte(c, k), v);
    }
    __syncthreads();

    const int ntiles = (nrows + TILE_M - 1) / TILE_M;
    const int lr0 = w * 16 + g;

    // loop-invariant base pointers; all LDS offsets below are compile-time immediates
    const char* pB1 = sm + g * 64  + q * 16;   // B1: + j*512 (+ 112*64 for loc tower)
    const char* pB2 = sm + g * 448 + q * 16;   // B2: + B2xOFF + j*3584 + ks*64

    for (int tile = blockIdx.x; tile < ntiles; tile += GRIDX) {
        const int grow0 = tile * TILE_M + lr0;
        const int grow1 = grow0 + 8;

        // ---- GEMM1 A-fragments from global s (K=16: s cols 0..9, bias at 10) ----
        uint32_t saH[4], saL[4];
        {
            float2 p0 = make_float2(0.f, 0.f), p1 = p0, e0 = p0, e1 = p0;
            if (grow0 < nrows) p0 = *(const float2*)(s + (size_t)grow0 * 10 + 2 * q);
            if (grow1 < nrows) p1 = *(const float2*)(s + (size_t)grow1 * 10 + 2 * q);
            if (q == 0) {
                if (grow0 < nrows) e0 = *(const float2*)(s + (size_t)grow0 * 10 + 8);
                if (grow1 < nrows) e1 = *(const float2*)(s + (size_t)grow1 * 10 + 8);
            } else if (q == 1) {
                e0.x = 1.0f; e1.x = 1.0f;
            }
            split_pack(p0.x, p0.y, saH[0], saL[0]);
            split_pack(p1.x, p1.y, saH[1], saL[1]);
            split_pack(e0.x, e0.y, saH[2], saL[2]);
            split_pack(e1.x, e1.y, saH[3], saL[3]);
        }

        // ======== GEMM1v: pair-interleaved d0/d1 (dep distance 2) ========
        uint32_t vaH[7][4], vaL[7][4];
        #pragma unroll
        for (int jp = 0; jp < 6; jp++) {
            float d0[4] = {0.f, 0.f, 0.f, 0.f}, d1[4] = {0.f, 0.f, 0.f, 0.f};
            uint4 b0 = *(const uint4*)(pB1 + (2 * jp) * 512);
            uint4 b1 = *(const uint4*)(pB1 + (2 * jp + 1) * 512);
            mma16816(d0, saH, b0.x, b0.y);
            mma16816(d1, saH, b1.x, b1.y);
            mma16816(d0, saH, b0.z, b0.w);
            mma16816(d1, saH, b1.z, b1.w);
            mma16816(d0, saL, b0.x, b0.y);
            mma16816(d1, saL, b1.x, b1.y);
            relu_split(d0[0], d0[1], vaH[jp][0], vaL[jp][0]);
            relu_split(d0[2], d0[3], vaH[jp][1], vaL[jp][1]);
            relu_split(d1[0], d1[1], vaH[jp][2], vaL[jp][2]);
            relu_split(d1[2], d1[3], vaH[jp][3], vaL[jp][3]);
        }
        {
            float d0[4] = {0.f, 0.f, 0.f, 0.f};
            uint4 bb = *(const uint4*)(pB1 + 12 * 512);
            mma16816(d0, saH, bb.x, bb.y);
            mma16816(d0, saH, bb.z, bb.w);
            mma16816(d0, saL, bb.x, bb.y);
            relu_split(d0[0], d0[1], vaH[6][0], vaL[6][0]);
            relu_split(d0[2], d0[3], vaH[6][1], vaL[6][1]);
        }
        if (q == 2) { vaH[6][0] = 0x3F80u; vaL[6][0] = 0u; vaH[6][1] = 0x3F80u; vaL[6][1] = 0u; }
        vaH[6][2] = 0u; vaH[6][3] = 0u; vaL[6][2] = 0u; vaL[6][3] = 0u;

        // ===== GEMM2v: j-pair interleaved + rolling pair prefetch =====
        float cv[7][4];
        #pragma unroll
        for (int j = 0; j < 7; j++) { cv[j][0]=0.f; cv[j][1]=0.f; cv[j][2]=0.f; cv[j][3]=0.f; }
        {
            const char* pv = pB2 + B2VOFF;
            uint4 c0 = *(const uint4*)(pv);          // (ks0, j0)
            uint4 c1 = *(const uint4*)(pv + 3584);   // (ks0, j1)
            #pragma unroll
            for (int ks = 0; ks < 7; ks++) {
                #pragma unroll
                for (int jp = 0; jp < 7; jp += 2) {   // 0,2,4,6(single)
                    const int njp = (jp < 6) ? jp + 2 : 0;
                    const int nks = (jp < 6) ? ks : ks + 1;
                    uint4 n0 = c0, n1 = c1;
                    if (nks < 7) {
                        n0 = *(const uint4*)(pv + nks * 64 + njp * 3584);
                        n1 = *(const uint4*)(pv + nks * 64 + (njp + 1) * 3584); // njp+1==7 reads pad region; unused
                    }
                    if (jp == 6) {
                        mma16816(cv[6], vaH[ks], c0.x, c0.y);
                        mma16816(cv[6], vaH[ks], c0.z, c0.w);
                        mma16816(cv[6], vaL[ks], c0.x, c0.y);
                    } else {
                        mma16816(cv[jp],     vaH[ks], c0.x, c0.y);
                        mma16816(cv[jp + 1], vaH[ks], c1.x, c1.y);
                        mma16816(cv[jp],     vaH[ks], c0.z, c0.w);
                        mma16816(cv[jp + 1], vaH[ks], c1.z, c1.w);
                        mma16816(cv[jp],     vaL[ks], c0.x, c0.y);
                        mma16816(cv[jp + 1], vaL[ks], c1.x, c1.y);
                    }
                    c0 = n0; c1 = n1;
                }
            }
        }

        // ======== GEMM1l: pair-interleaved (va dead would be wrong — va live; dl pairs only) ========
        uint32_t laH[7][4], laL[7][4];
        #pragma unroll
        for (int jp = 0; jp < 6; jp++) {
            float d0[4] = {0.f, 0.f, 0.f, 0.f}, d1[4] = {0.f, 0.f, 0.f, 0.f};
            uint4 b0 = *(const uint4*)(pB1 + 112 * 64 + (2 * jp) * 512);
            uint4 b1 = *(const uint4*)(pB1 + 112 * 64 + (2 * jp + 1) * 512);
            mma16816(d0, saH, b0.x, b0.y);
            mma16816(d1, saH, b1.x, b1.y);
            mma16816(d0, saH, b0.z, b0.w);
            mma16816(d1, saH, b1.z, b1.w);
            mma16816(d0, saL, b0.x, b0.y);
            mma16816(d1, saL, b1.x, b1.y);
            relu_split(d0[0], d0[1], laH[jp][0], laL[jp][0]);
            relu_split(d0[2], d0[3], laH[jp][1], laL[jp][1]);
            relu_split(d1[0], d1[1], laH[jp][2], laL[jp][2]);
            relu_split(d1[2], d1[3], laH[jp][3], laL[jp][3]);
        }
        {
            float d0[4] = {0.f, 0.f, 0.f, 0.f};
            uint4 bb = *(const uint4*)(pB1 + 112 * 64 + 12 * 512);
            mma16816(d0, saH, bb.x, bb.y);
            mma16816(d0, saH, bb.z, bb.w);
            mma16816(d0, saL, bb.x, bb.y);
            relu_split(d0[0], d0[1], laH[6][0], laL[6][0]);
            relu_split(d0[2], d0[3], laH[6][1], laL[6][1]);
        }
        if (q == 2) { laH[6][0] = 0x3F80u; laL[6][0] = 0u; laH[6][1] = 0x3F80u; laL[6][1] = 0u; }
        laH[6][2] = 0u; laH[6][3] = 0u; laL[6][2] = 0u; laL[6][3] = 0u;

        // action rows
        float2 av0 = make_float2(0.f, 0.f), av1 = av0;
        if (grow0 < nrows) av0 = ((const float2*)a)[grow0];
        if (grow1 < nrows) av1 = ((const float2*)a)[grow1];

        // ===== GEMM2l: j-pairs interleaved, epilogue fused per pair =====
        float ws0 = 0.f, vs0 = 0.f, ws1 = 0.f, vs1 = 0.f;
        {
            const char* pl = pB2 + B2LOFF;
            uint4 c0 = *(const uint4*)(pl);          // (j0, ks0)
            uint4 c1 = *(const uint4*)(pl + 3584);   // (j1, ks0)
            #pragma unroll
            for (int jp = 0; jp < 13; jp += 2) {     // 0,2,...,10,12(single)
                float l0[4] = {0.f, 0.f, 0.f, 0.f}, l1[4] = {0.f, 0.f, 0.f, 0.f};
                #pragma unroll
                for (int ks = 0; ks < 7; ks++) {
                    const int nks = (ks < 6) ? ks + 1 : 0;
                    const int njp = (ks < 6) ? jp : jp + 2;
                    uint4 n0 = c0, n1 = c1;
                    if (njp < 13) {
                        n0 = *(const uint4*)(pl + njp * 3584 + nks * 64);
                        n1 = (njp < 12)
                           ? *(const uint4*)(pl + (njp + 1) * 3584 + nks * 64)
                           : n0;   // j=12 single: second slot unused
                    }
                    if (jp == 12) {
                        mma16816(l0, laH[ks], c0.x, c0.y);
                        mma16816(l0, laH[ks], c0.z, c0.w);
                        mma16816(l0, laL[ks], c0.x, c0.y);
                    } else {
                        mma16816(l0, laH[ks], c0.x, c0.y);
                        mma16816(l1, laH[ks], c1.x, c1.y);
                        mma16816(l0, laH[ks], c0.z, c0.w);
                        mma16816(l1, laH[ks], c1.z, c1.w);
                        mma16816(l0, laL[ks], c0.x, c0.y);
                        mma16816(l1, laL[ks], c1.x, c1.y);
                    }
                    c0 = n0; c1 = n1;
                }
                // fused epilogue for j=jp (and jp+1 when present)
                #pragma unroll
                for (int u = 0; u < 2; u++) {
                    const int j = jp + u;
                    if (j < 13) {
                        const float* lc = (u == 0) ? l0 : l1;
                        const bool valid = (4 * j + q) < 50;
                        {
                            float tx = MAXA * fast_tanh(lc[0]) - av0.x;
                            float ty = MAXA * fast_tanh(lc[1]) - av0.y;
                            float e = valid ? __expf(-BETA * sqrtf(tx * tx + ty * ty)) : 0.f;
                            float cc = (j & 1) ? cv[j >> 1][1] : cv[j >> 1][0];
                            ws0 += e; vs0 += e * cc;
                        }
                        {
                            float tx = MAXA * fast_tanh(lc[2]) - av1.x;
                            float ty = MAXA * fast_tanh(lc[3]) - av1.y;
                            float e = valid ? __expf(-BETA * sqrtf(tx * tx + ty * ty)) : 0.f;
                            float cc = (j & 1) ? cv[j >> 1][3] : cv[j >> 1][2];
                            ws1 += e; vs1 += e * cc;
                        }
                    }
                }
            }
        }

        ws0 += __shfl_xor_sync(0xffffffffu, ws0, 1);
        vs0 += __shfl_xor_sync(0xffffffffu, vs0, 1);
        ws1 += __shfl_xor_sync(0xffffffffu, ws1, 1);
        vs1 += __shfl_xor_sync(0xffffffffu, vs1, 1);
        ws0 += __shfl_xor_sync(0xffffffffu, ws0, 2);
        vs0 += __shfl_xor_sync(0xffffffffu, vs0, 2);
        ws1 += __shfl_xor_sync(0xffffffffu, ws1, 2);
        vs1 += __shfl_xor_sync(0xffffffffu, vs1, 2);
        if (q == 0) {
            if (grow0 < nrows) out[grow0] = vs0 / ws0;
            if (grow1 < nrows) out[grow1] = vs1 / ws1;
        }
    }
}

extern "C" void kernel_launch(void* const* d_in, const int* in_sizes, int n_in,
                              void* d_out, int out_size)
{
    const float* s   = (const float*)d_in[0];
    const float* a   = (const float*)d_in[1];
    const float* wv1 = (const float*)d_in[2];
    const float* bv1 = (const float*)d_in[3];
    const float* wv2 = (const float*)d_in[4];
    const float* bv2 = (const float*)d_in[5];
    const float* wl1 = (const float*)d_in[6];
    const float* bl1 = (const float*)d_in[7];
    const float* wl2 = (const float*)d_in[8];
    const float* bl2 = (const float*)d_in[9];
    float* out = (float*)d_out;

    int nrows = in_sizes[0] / 10;

    cudaFuncSetAttribute(net_kernel, cudaFuncAttributeMaxDynamicSharedMemorySize, SMEM_BYTES);
    net_kernel<<<GRIDX, TPB, SMEM_BYTES>>>(s, a, wv1, bv1, wv2, bv2,
                                           wl1, bl1, wl2, bl2, out, nrows);
}